// round 6
// baseline (speedup 1.0000x reference)
#include <cuda_runtime.h>
#include <cuda_fp16.h>
#include <math.h>
#include <stdint.h>

// Problem constants (fixed by the reference)
#define TOK   8192          // B*S tokens
#define DDIM  1024
#define NEXP  8
#define HDIM  2048
#define RROWS (2*TOK)       // routed rows (top_k = 2)
#define MAXT  144           // >= worst-case sum of ceil(n_e/128) = 135
#define SLAB  (DDIM*HDIM)   // per-expert weight elements (same for W1 and W2)

// ------------------------- device scratch (no cudaMalloc allowed) ----------
static __device__ __half g_xh [(size_t)TOK   * DDIM];   // x in fp16
static __device__ __half g_W1t[(size_t)NEXP * SLAB];    // W1^T fp16: [e][h][d]
static __device__ __half g_W2t[(size_t)NEXP * SLAB];    // W2^T fp16: [e][d][h]
static __device__ __half g_Hh [(size_t)RROWS * HDIM];   // FFN1 output, fp16
static __device__ float  g_Y  [(size_t)RROWS * DDIM];   // FFN2 output, fp32
static __device__ int    g_eidx[2 * TOK];
static __device__ float  g_ew[2 * TOK];
static __device__ int    g_perm[RROWS];
static __device__ int    g_tokpos[2 * TOK];
static __device__ int    g_cnt[NEXP];
static __device__ int    g_off[NEXP + 1];
static __device__ int    g_cur[NEXP];
static __device__ int    g_ntiles;
static __device__ int    g_te[MAXT], g_tr0[MAXT], g_tnr[MAXT];

// ------------------------- small helpers -----------------------------------
__device__ __forceinline__ void mma16(float* c, const uint32_t* a, const uint32_t* b) {
    asm volatile(
        "mma.sync.aligned.m16n8k16.row.col.f32.f16.f16.f32 "
        "{%0,%1,%2,%3},{%4,%5,%6,%7},{%8,%9},{%0,%1,%2,%3};"
        : "+f"(c[0]), "+f"(c[1]), "+f"(c[2]), "+f"(c[3])
        : "r"(a[0]), "r"(a[1]), "r"(a[2]), "r"(a[3]), "r"(b[0]), "r"(b[1]));
}

__device__ __forceinline__ float gelu_t(float v) {
    // matches jax.nn.gelu(approximate=True)
    float u = 0.7978845608028654f * (v + 0.044715f * v * v * v);
    return 0.5f * v * (1.0f + tanhf(u));
}

// ------------------------- conversion kernels -------------------------------
__global__ void k_xcvt(const float* __restrict__ x) {
    size_t i = (size_t)blockIdx.x * 256 + threadIdx.x;   // over TOK*DDIM/4
    float4 v = ((const float4*)x)[i];
    __half2* dst = (__half2*)g_xh;
    dst[2 * i]     = __floats2half2_rn(v.x, v.y);
    dst[2 * i + 1] = __floats2half2_rn(v.z, v.w);
}

// Transpose + convert: in fp32 [E][K][N] -> out fp16 [E][N][K]
template <bool TO_W1>
__global__ void k_tcvt(const float* __restrict__ in, int K, int N) {
    __shared__ float t[32][33];
    int e = blockIdx.z;
    int n0 = blockIdx.x * 32, k0 = blockIdx.y * 32;
    const float* ip = in + (size_t)e * K * N;
    __half* op = (TO_W1 ? g_W1t : g_W2t) + (size_t)e * (size_t)K * N;
    int tx = threadIdx.x, ty = threadIdx.y;  // 32 x 8
#pragma unroll
    for (int i = 0; i < 32; i += 8)
        t[ty + i][tx] = ip[(size_t)(k0 + ty + i) * N + n0 + tx];
    __syncthreads();
#pragma unroll
    for (int i = 0; i < 32; i += 8)
        op[(size_t)(n0 + ty + i) * K + k0 + tx] = __float2half(t[tx][ty + i]);
}

// ------------------------- routing kernels ----------------------------------
__global__ void k_init() {
    int i = threadIdx.x;
    if (i < NEXP) g_cnt[i] = 0;
}

// Gating: logits = x @ Wg + bg, top-2 renormalized softmax weights.
__global__ void k_gate(const float* __restrict__ x,
                       const float* __restrict__ Wg,
                       const float* __restrict__ bg) {
    __shared__ float sW[DDIM * NEXP];
    __shared__ float sb[NEXP];
    for (int i = threadIdx.x; i < DDIM * NEXP; i += 256) sW[i] = Wg[i];
    if (threadIdx.x < NEXP) sb[threadIdx.x] = bg[threadIdx.x];
    __syncthreads();

    int w = threadIdx.x >> 5, lane = threadIdx.x & 31;
    int t = blockIdx.x * 8 + w;
    const float* xr = x + (size_t)t * DDIM;

    float acc[NEXP];
#pragma unroll
    for (int e = 0; e < NEXP; e++) acc[e] = 0.0f;
    for (int k = lane; k < DDIM; k += 32) {
        float xv = xr[k];
#pragma unroll
        for (int e = 0; e < NEXP; e++) acc[e] = fmaf(xv, sW[k * NEXP + e], acc[e]);
    }
#pragma unroll
    for (int e = 0; e < NEXP; e++) {
#pragma unroll
        for (int o = 16; o > 0; o >>= 1)
            acc[e] += __shfl_xor_sync(0xffffffffu, acc[e], o);
    }
    if (lane == 0) {
        float l[NEXP];
#pragma unroll
        for (int e = 0; e < NEXP; e++) l[e] = acc[e] + sb[e];
        int i0 = 0;
#pragma unroll
        for (int e = 1; e < NEXP; e++) if (l[e] > l[i0]) i0 = e;
        int i1 = (i0 == 0) ? 1 : 0;
#pragma unroll
        for (int e = 0; e < NEXP; e++) if (e != i0 && l[e] > l[i1]) i1 = e;
        float w0 = 1.0f / (1.0f + expf(l[i1] - l[i0]));
        g_eidx[2 * t]     = i0;
        g_eidx[2 * t + 1] = i1;
        g_ew[2 * t]       = w0;
        g_ew[2 * t + 1]   = 1.0f - w0;
        atomicAdd(&g_cnt[i0], 1);
        atomicAdd(&g_cnt[i1], 1);
    }
}

__global__ void k_offsets() {
    if (threadIdx.x == 0) {
        int off = 0, nt = 0;
        for (int e = 0; e < NEXP; e++) {
            g_off[e] = off;
            g_cur[e] = 0;
            int c = g_cnt[e];
            int tiles = (c + 127) >> 7;
            for (int m = 0; m < tiles; m++) {
                g_te[nt]  = e;
                g_tr0[nt] = off + m * 128;
                int nr = c - m * 128;
                if (nr > 128) nr = 128;
                g_tnr[nt] = nr;
                nt++;
            }
            off += c;
        }
        g_off[NEXP] = off;
        g_ntiles = nt;
    }
}

__global__ void k_scatter() {
    int t = blockIdx.x * blockDim.x + threadIdx.x;
    if (t >= TOK) return;
#pragma unroll
    for (int k = 0; k < 2; k++) {
        int e = g_eidx[2 * t + k];
        int p = g_off[e] + atomicAdd(&g_cur[e], 1);
        g_perm[p] = t;
        g_tokpos[2 * t + k] = p;
    }
}

// -------- grouped GEMM: C[tile] = act(A @ B[e]^T + bias[e]) -----------------
// 128x128 CTA tile, BK=32 halves, 256 threads, warp tile 64x32, m16n8k16 f16.
// A smem [m][k], B smem [n][k] (weights pre-transposed to n-major).
// Row stride 40 halves (20 words): all STS.128 and fragment LDS.32 are
// bank-conflict-free ({0,20,8,28,16,4,24,12}+{0..3} tiles all 32 banks).
template <int KDIM, int NDIM, bool GATHER, bool GELU>
__global__ __launch_bounds__(256, 2) void k_gemm(const float* __restrict__ biasg) {
    int jt = blockIdx.y;
    if (jt >= g_ntiles) return;
    int e = g_te[jt], row0 = g_tr0[jt], nrows = g_tnr[jt];
    int n0 = blockIdx.x * 128;

    const __half* Bt = (GELU ? g_W1t : g_W2t) + (size_t)e * SLAB;
    const float*  bp = biasg + (size_t)e * NDIM;

    __shared__ __align__(16) __half As[2][128][40];
    __shared__ __align__(16) __half Bs[2][128][40];

    int tid  = threadIdx.x;
    int lane = tid & 31, warp = tid >> 5;
    int wm = warp & 1, wn = warp >> 1;     // warp grid 2(M) x 4(N)
    int grp = lane >> 2, tig = lane & 3;

    // loader assignment: row lr (0..127), 16-half chunk lc (0/1)
    int lr = tid & 127, lc = tid >> 7;
    int gr = row0 + lr; if (gr > RROWS - 1) gr = RROWS - 1;
    const __half* pA;
    if (GATHER) pA = g_xh + (size_t)g_perm[gr] * KDIM + lc * 16;
    else        pA = g_Hh + (size_t)gr * KDIM + lc * 16;
    const __half* pB = Bt + (size_t)(n0 + lr) * KDIM + lc * 16;

    float acc[4][4][4];
#pragma unroll
    for (int mi = 0; mi < 4; mi++)
#pragma unroll
        for (int ni = 0; ni < 4; ni++)
#pragma unroll
            for (int q = 0; q < 4; q++) acc[mi][ni][q] = 0.0f;

    uint4 va0, va1, vb0, vb1;

    auto ldg = [&]() {
        va0 = *(const uint4*)pA;       va1 = *(const uint4*)(pA + 8);
        vb0 = *(const uint4*)pB;       vb1 = *(const uint4*)(pB + 8);
        pA += 32;  pB += 32;
    };
    auto sts = [&](int b) {
        *(uint4*)&As[b][lr][lc * 16]     = va0;
        *(uint4*)&As[b][lr][lc * 16 + 8] = va1;
        *(uint4*)&Bs[b][lr][lc * 16]     = vb0;
        *(uint4*)&Bs[b][lr][lc * 16 + 8] = vb1;
    };

    ldg();
    sts(0);
    __syncthreads();

    const int NIT = KDIM / 32;
    int buf = 0;
    for (int kt = 0; kt < NIT; kt++) {
        if (kt + 1 < NIT) ldg();
#pragma unroll
        for (int s = 0; s < 2; s++) {
            int kh = s * 16 + 2 * tig;   // half index within BK
            uint32_t af[4][4];
            uint32_t bf[4][2];
#pragma unroll
            for (int mi = 0; mi < 4; mi++) {
                int m = wm * 64 + mi * 16 + grp;
                af[mi][0] = *(const uint32_t*)&As[buf][m][kh];
                af[mi][1] = *(const uint32_t*)&As[buf][m + 8][kh];
                af[mi][2] = *(const uint32_t*)&As[buf][m][kh + 8];
                af[mi][3] = *(const uint32_t*)&As[buf][m + 8][kh + 8];
            }
#pragma unroll
            for (int ni = 0; ni < 4; ni++) {
                int n = wn * 32 + ni * 8 + grp;
                bf[ni][0] = *(const uint32_t*)&Bs[buf][n][kh];
                bf[ni][1] = *(const uint32_t*)&Bs[buf][n][kh + 8];
            }
#pragma unroll
            for (int mi = 0; mi < 4; mi++)
#pragma unroll
                for (int ni = 0; ni < 4; ni++)
                    mma16(acc[mi][ni], af[mi], bf[ni]);
        }
        if (kt + 1 < NIT) sts(buf ^ 1);
        __syncthreads();
        buf ^= 1;
    }

    // epilogue
#pragma unroll
    for (int mi = 0; mi < 4; mi++) {
        int r = wm * 64 + mi * 16 + grp;
#pragma unroll
        for (int ni = 0; ni < 4; ni++) {
            int nc = n0 + wn * 32 + ni * 8 + 2 * tig;
            float bb0 = bp[nc], bb1 = bp[nc + 1];
            float v0 = acc[mi][ni][0] + bb0, v1 = acc[mi][ni][1] + bb1;
            float v2 = acc[mi][ni][2] + bb0, v3 = acc[mi][ni][3] + bb1;
            if (GELU) {
                v0 = gelu_t(v0); v1 = gelu_t(v1);
                v2 = gelu_t(v2); v3 = gelu_t(v3);
                if (r < nrows)
                    *(__half2*)&g_Hh[(size_t)(row0 + r) * NDIM + nc] =
                        __floats2half2_rn(v0, v1);
                if (r + 8 < nrows)
                    *(__half2*)&g_Hh[(size_t)(row0 + r + 8) * NDIM + nc] =
                        __floats2half2_rn(v2, v3);
            } else {
                if (r < nrows)
                    *(float2*)&g_Y[(size_t)(row0 + r) * NDIM + nc] =
                        make_float2(v0, v1);
                if (r + 8 < nrows)
                    *(float2*)&g_Y[(size_t)(row0 + r + 8) * NDIM + nc] =
                        make_float2(v2, v3);
            }
        }
    }
}

// out[t] = w0 * Y[pos0(t)] + w1 * Y[pos1(t)]
__global__ void k_combine(float* __restrict__ out) {
    int idx = blockIdx.x * 256 + threadIdx.x;    // over TOK * DDIM / 4
    int t  = idx >> 8;                           // DDIM/4 = 256
    int dq = idx & 255;
    int p0 = g_tokpos[2 * t], p1 = g_tokpos[2 * t + 1];
    float w0 = g_ew[2 * t], w1 = g_ew[2 * t + 1];
    const float4* Y = (const float4*)g_Y;
    float4 a = Y[(size_t)p0 * 256 + dq];
    float4 b = Y[(size_t)p1 * 256 + dq];
    float4 r;
    r.x = w0 * a.x + w1 * b.x;
    r.y = w0 * a.y + w1 * b.y;
    r.z = w0 * a.z + w1 * b.z;
    r.w = w0 * a.w + w1 * b.w;
    ((float4*)out)[idx] = r;
}

// ------------------------- launch ------------------------------------------
extern "C" void kernel_launch(void* const* d_in, const int* in_sizes, int n_in,
                              void* d_out, int out_size) {
    // metadata order: x, top_k(scalar, maybe absent), Wg, bg, W1, b1, W2, b2
    int base = (n_in >= 8) ? 1 : 0;
    const float* x  = (const float*)d_in[0];
    const float* Wg = (const float*)d_in[base + 1];
    const float* bg = (const float*)d_in[base + 2];
    const float* W1 = (const float*)d_in[base + 3];
    const float* b1 = (const float*)d_in[base + 4];
    const float* W2 = (const float*)d_in[base + 5];
    const float* b2 = (const float*)d_in[base + 6];
    float* out = (float*)d_out;
    (void)in_sizes; (void)out_size;

    k_init<<<1, 32>>>();
    // operand preparation (fp16 convert; weights transposed to n-major)
    k_xcvt<<<(TOK * DDIM / 4) / 256, 256>>>(x);
    k_tcvt<true ><<<dim3(HDIM / 32, DDIM / 32, NEXP), dim3(32, 8)>>>(W1, DDIM, HDIM);
    k_tcvt<false><<<dim3(DDIM / 32, HDIM / 32, NEXP), dim3(32, 8)>>>(W2, HDIM, DDIM);
    // routing
    k_gate<<<TOK / 8, 256>>>(x, Wg, bg);
    k_offsets<<<1, 32>>>();
    k_scatter<<<(TOK + 255) / 256, 256>>>();
    // FFN1: gathered x rows @ W1^T, gelu -> g_Hh (fp16)
    k_gemm<DDIM, HDIM, true,  true ><<<dim3(HDIM / 128, MAXT), 256>>>(b1);
    // FFN2: g_Hh @ W2^T -> g_Y (fp32)
    k_gemm<HDIM, DDIM, false, false><<<dim3(DDIM / 128, MAXT), 256>>>(b2);
    // weighted combine
    k_combine<<<(TOK * DDIM / 4) / 256, 256>>>(out);
}